// round 14
// baseline (speedup 1.0000x reference)
#include <cuda_runtime.h>
#include <cuda_bf16.h>
typedef unsigned u32; typedef unsigned long long u64; typedef unsigned short u16;
#define NBLK 128
#define NTHR 256
#define TT 1024
#define HH 512

// h stored pre-split: separate bf16 hi and lo planes, [batch][k]
__device__ __align__(16) u16 g_h1h[2][128 * HH], g_h1l[2][128 * HH];
__device__ __align__(16) u16 g_h2h[128 * HH],    g_h2l[128 * HH];
__device__ float g_xt[TT * 128];
__device__ u32 g_cnt, g_epoch, g_dead;

// smem layout (bytes)
#define O_W1  0          // weight tile: hi 16x1024B, lo at +16384 (32KB per matrix)
#define O_H2  32768
#define O_I2  65536
#define O_STG 98304      // 3 slots x 32768 (hi 16KB + lo 16KB), rows 128B swizzled
#define O_G   196608     // gates exchange: 16 x 132 f32 = 8448
#define O_WX  205056
#define O_BB1 205120
#define O_BB2 205184
#define O_RED 205248     // 256 f32
#define SMEMSZ 206336

__device__ __forceinline__ float sigf(float v){ return __fdividef(1.f, 1.f + __expf(-v)); }
__device__ __forceinline__ u32 s2u(const void* p){ u32 a; asm("{.reg .u64 t;cvta.to.shared.u64 t,%1;cvt.u32.u64 %0,t;}":"=r"(a):"l"(p)); return a; }
__device__ __forceinline__ u32 ldcg32(const void* p){ u32 v; asm volatile("ld.global.cg.u32 %0,[%1];":"=r"(v):"l"(p)); return v; }
__device__ __forceinline__ float bfv(u32 b){ u16 s=(u16)b; __nv_bfloat16 h=*(__nv_bfloat16*)&s; return __bfloat162float(h); }
__device__ __forceinline__ u16 tob(float f){ __nv_bfloat16 h=__float2bfloat16(f); return *(u16*)&h; }
__device__ __forceinline__ void ldm4(u32* r, u32 a){
  asm volatile("ldmatrix.sync.aligned.m8n8.x4.shared.b16 {%0,%1,%2,%3},[%4];"
    :"=r"(r[0]),"=r"(r[1]),"=r"(r[2]),"=r"(r[3]):"r"(a)); }
__device__ __forceinline__ void mma16816(float* c, const u32* a, const u32* b){
  asm volatile("mma.sync.aligned.m16n8k16.row.col.f32.bf16.bf16.f32 "
    "{%0,%1,%2,%3},{%4,%5,%6,%7},{%8,%9},{%0,%1,%2,%3};"
    :"+f"(c[0]),"+f"(c[1]),"+f"(c[2]),"+f"(c[3])
    :"r"(a[0]),"r"(a[1]),"r"(a[2]),"r"(a[3]),"r"(b[0]),"r"(b[1])); }
__device__ __forceinline__ void cpa16(u32 dst, const void* src){
  asm volatile("cp.async.cg.shared.global [%0],[%1],16;"::"r"(dst),"l"(src)); }
#define CPA_COMMIT() asm volatile("cp.async.commit_group;":::"memory")
#define CPA_WAIT0()  asm volatile("cp.async.wait_group 0;":::"memory")
#define CPA_WAIT1()  asm volatile("cp.async.wait_group 1;":::"memory")

// grid barrier with deadlock poison (proven R11-R13)
__device__ __forceinline__ void gridbar(){
  __syncthreads();
  if(threadIdx.x==0){
    u32 dead; asm volatile("ld.relaxed.gpu.u32 %0,[%1];":"=r"(dead):"l"(&g_dead));
    if(!dead){
      u32 e; asm volatile("ld.acquire.gpu.u32 %0,[%1];":"=r"(e):"l"(&g_epoch));
      u32 r; asm volatile("atom.add.release.gpu.u32 %0,[%1],%2;":"=r"(r):"l"(&g_cnt),"r"(1u));
      if(r==NBLK-1){
        asm volatile("st.relaxed.gpu.u32 [%0],%1;"::"l"(&g_cnt),"r"(0u));
        asm volatile("red.release.gpu.add.u32 [%0],%1;"::"l"(&g_epoch),"r"(1u));
      } else {
        u32 c, it=0;
        do{
          asm volatile("ld.acquire.gpu.u32 %0,[%1];":"=r"(c):"l"(&g_epoch));
          if(c!=e) break;
          asm volatile("ld.relaxed.gpu.u32 %0,[%1];":"=r"(dead):"l"(&g_dead));
          if(dead) break;
          if(++it > 20000000u){ atomicExch(&g_dead,1u); break; }
        } while(1);
      }
    }
  }
  __syncthreads();
}

// issue cp.async copies for chunk c of (hiP, loP) -> swizzled stage slot
__device__ __forceinline__ void stage_issue(u32 stg, const u16* hiP, const u16* loP,
                                            int c, int tid){
#pragma unroll
  for(int i=0;i<8;i++){
    int u = tid + i*256;              // 0..2047
    int p = u>>10;                    // 0 = hi plane, 1 = lo plane
    int row = (u>>3)&127;
    int atom = u&7;
    const u16* src = (p ? loP : hiP) + row*HH + c*64 + atom*8;
    u32 dst = stg + (u32)(p*16384 + row*128 + (((atom ^ (row&7)))<<4));
    cpa16(dst, src);
  }
  CPA_COMMIT();
}

// one 64-k chunk: 4 kt x (A hi/lo ldm4 + B hi/lo ldm4(2 n-tiles) + 6 mma)
__device__ __forceinline__ void gemm_chunk(u32 smb, int wbase, u32 stg, int c,
                                           int lane, int warp, float C[2][4]){
  const int krow = lane&15, khalf = lane>>4;
  const int brow = warp*16 + ((lane>>4)<<3) + (lane&7);
  const int bk   = (lane>>3)&1;
#pragma unroll
  for(int kt=0;kt<4;kt++){
    int aatom = c*8 + kt*2 + khalf;
    u32 aa = smb + (u32)wbase + (u32)(krow*1024) + (u32)(((aatom^(krow&7)))<<4);
    u32 ah[4], al[4]; ldm4(ah,aa); ldm4(al,aa+16384);
    int batom = kt*2 + bk;
    u32 ba = stg + (u32)(brow*128) + (u32)(((batom^(brow&7)))<<4);
    u32 bh[4], bl[4]; ldm4(bh,ba); ldm4(bl,ba+16384);
    mma16816(C[0],ah,bh);   mma16816(C[0],ah,bl);   mma16816(C[0],al,bh);
    mma16816(C[1],ah,bh+2); mma16816(C[1],ah,bl+2); mma16816(C[1],al,bh+2);
  }
}

// fused phase A: 16 chunks (q<8: Whh1*h1 -> C1 ; q>=8: Whh2*h2 -> C2), depth-2 pipeline
__device__ __forceinline__ void phaseA(u32 smb, const u16* h1h, const u16* h1l,
                                       float C1[2][4], float C2[2][4],
                                       int tid, int lane, int warp){
  stage_issue(smb+O_STG,        h1h, h1l, 0, tid);
  stage_issue(smb+O_STG+32768u, h1h, h1l, 1, tid);
#pragma unroll 1
  for(int q=0;q<16;q++){
    if(q==15){ CPA_WAIT0(); } else { CPA_WAIT1(); }
    __syncthreads();   // chunk q staged; all warps done with mma(q-1) -> slot (q+2)%3 free
    if(q<14){
      int qq=q+2; u32 slot = smb+O_STG+(u32)((qq%3)*32768);
      if(qq<8) stage_issue(slot, h1h,  h1l,  qq,   tid);
      else     stage_issue(slot, g_h2h, g_h2l, qq-8, tid);
    }
    u32 slot = smb+O_STG+(u32)((q%3)*32768);
    if(q<8) gemm_chunk(smb, O_W1, slot, q,   lane, warp, C1);
    else    gemm_chunk(smb, O_H2, slot, q-8, lane, warp, C2);
  }
}
// phase B: 8 chunks (Wih2*h1_new -> C2), depth-2 pipeline
__device__ __forceinline__ void phaseB(u32 smb, const u16* hh, const u16* hl,
                                       float C2[2][4], int tid, int lane, int warp){
  stage_issue(smb+O_STG,        hh, hl, 0, tid);
  stage_issue(smb+O_STG+32768u, hh, hl, 1, tid);
#pragma unroll 1
  for(int q=0;q<8;q++){
    if(q==7){ CPA_WAIT0(); } else { CPA_WAIT1(); }
    __syncthreads();
    if(q<6) stage_issue(smb+O_STG+(u32)(((q+2)%3)*32768), hh, hl, q+2, tid);
    gemm_chunk(smb, O_I2, smb+O_STG+(u32)((q%3)*32768), q, lane, warp, C2);
  }
}

__global__ void __launch_bounds__(NTHR,1)
lstm_mma(const float* __restrict__ x, const float* __restrict__ Wih1, const float* __restrict__ Whh1,
         const float* __restrict__ bih1, const float* __restrict__ bhh1,
         const float* __restrict__ Wih2, const float* __restrict__ Whh2,
         const float* __restrict__ bih2, const float* __restrict__ bhh2,
         const float* __restrict__ Wlin, const float* __restrict__ blin, float* __restrict__ out){
  extern __shared__ __align__(128) char sm[];
  const int tid=threadIdx.x, blk=blockIdx.x, warp=tid>>5, lane=tid&31;
  const u32 smb = s2u(sm);

  // x transpose (each block its 8 t-columns)
  for(int i=tid;i<1024;i+=NTHR){ int t=blk*8+(i>>7), b=i&127; g_xt[t*128+b]=x[b*TT+t]; }
  // weights -> smem bf16 hi/lo, 1024B rows, swizzled atoms
  { const float* WS[3]={Whh1,Whh2,Wih2}; const int WO[3]={O_W1,O_H2,O_I2};
    for(int m=0;m<3;m++) for(int idx=tid; idx<16*HH; idx+=NTHR){
      int s=idx&15, k=idx>>4; int r=(s&3)*HH + blk*4 + (s>>2);
      float w=WS[m][r*HH+k]; u16 hb=tob(w); u16 lb=tob(w-bfv(hb));
      u32 off=(u32)(s*1024) + (u32)((((k>>3)^(s&7))<<4)) + (u32)((k&7)*2);
      *(u16*)(sm+WO[m]+off)=hb; *(u16*)(sm+WO[m]+16384+off)=lb; } }
  if(tid<16){ int s=tid, r=(s&3)*HH + blk*4 + (s>>2);
    ((float*)(sm+O_WX))[s]=Wih1[r];
    ((float*)(sm+O_BB1))[s]=bih1[r]+bhh1[r];
    ((float*)(sm+O_BB2))[s]=bih2[r]+bhh2[r]; }
  const float wl0=Wlin[tid*2], wl1=Wlin[tid*2+1], blinv=blin[0];
  for(int i=tid;i<512;i+=NTHR){ int b=i>>2, c=i&3; int o=b*HH+blk*4+c;
    g_h1h[0][o]=0; g_h1l[0][o]=0; g_h2h[o]=0; g_h2l[o]=0; }
  __syncthreads();
  gridbar();

  float c1s[4]={0,0,0,0}, c2s[4]={0,0,0,0};   // cells: threads 0-127, batch=tid, 4 cols

  for(int t=0;t<TT;t++){
    const u16* h1rh = g_h1h[t&1];      const u16* h1rl = g_h1l[t&1];
    u16* h1wh = g_h1h[(t&1)^1];        u16* h1wl = g_h1l[(t&1)^1];

    // out[t-1] partials (h2 stable since last gridbar)
    if(t>0){
      u32 ph=ldcg32((const char*)g_h2h + blk*1024 + tid*4);
      u32 pl=ldcg32((const char*)g_h2l + blk*1024 + tid*4);
      ((float*)(sm+O_RED))[tid]=(bfv(ph)+bfv(pl))*wl0+(bfv(ph>>16)+bfv(pl>>16))*wl1;
    }

    float C1[2][4]={{0,0,0,0},{0,0,0,0}}, C2[2][4]={{0,0,0,0},{0,0,0,0}};
    phaseA(smb, h1rh, h1rl, C1, C2, tid, lane, warp);

    // epilogue A: exchange C1 -> G
    { float* G=(float*)(sm+O_G);
#pragma unroll
      for(int nt=0;nt<2;nt++){ int n0=warp*16+nt*8+(lane&3)*2; int rr=lane>>2;
        *(float2*)&G[rr*132+n0]     = make_float2(C1[nt][0],C1[nt][1]);
        *(float2*)&G[(rr+8)*132+n0] = make_float2(C1[nt][2],C1[nt][3]); } }
    __syncthreads();
    if(t>0 && warp==7){ float* R=(float*)(sm+O_RED); float sv=0.f;
#pragma unroll
      for(int j=0;j<8;j++) sv+=R[lane+j*32];
      for(int o=16;o;o>>=1) sv+=__shfl_down_sync(~0u,sv,o);
      if(lane==0) out[blk*TT+t-1]=sv+blinv; }
    if(tid<128){
      float* G=(float*)(sm+O_G); float* WX=(float*)(sm+O_WX); float* B1=(float*)(sm+O_BB1);
      int b=tid; float xv=g_xt[t*128+b];
      u16 hh[4], hl[4];
#pragma unroll
      for(int cl=0;cl<4;cl++){ int s0=cl*4;
        float gi=G[(s0+0)*132+b]+B1[s0+0]+xv*WX[s0+0];
        float gf=G[(s0+1)*132+b]+B1[s0+1]+xv*WX[s0+1];
        float gg=G[(s0+2)*132+b]+B1[s0+2]+xv*WX[s0+2];
        float go=G[(s0+3)*132+b]+B1[s0+3]+xv*WX[s0+3];
        float cn=sigf(gf)*c1s[cl]+sigf(gi)*tanhf(gg); c1s[cl]=cn;
        float h=sigf(go)*tanhf(cn);
        hh[cl]=tob(h); hl[cl]=tob(h-bfv(hh[cl])); }
      *(ushort4*)&h1wh[b*HH+blk*4]=make_ushort4(hh[0],hh[1],hh[2],hh[3]);
      *(ushort4*)&h1wl[b*HH+blk*4]=make_ushort4(hl[0],hl[1],hl[2],hl[3]);
    }
    gridbar();   // h1[t] visible everywhere

    // phase B: gates2 += Wih2 * h1_new
    phaseB(smb, h1wh, h1wl, C2, tid, lane, warp);

    { float* G=(float*)(sm+O_G);
#pragma unroll
      for(int nt=0;nt<2;nt++){ int n0=warp*16+nt*8+(lane&3)*2; int rr=lane>>2;
        *(float2*)&G[rr*132+n0]     = make_float2(C2[nt][0],C2[nt][1]);
        *(float2*)&G[(rr+8)*132+n0] = make_float2(C2[nt][2],C2[nt][3]); } }
    __syncthreads();
    if(tid<128){
      float* G=(float*)(sm+O_G); float* B2=(float*)(sm+O_BB2);
      int b=tid;
      u16 hh[4], hl[4];
#pragma unroll
      for(int cl=0;cl<4;cl++){ int s0=cl*4;
        float gi=G[(s0+0)*132+b]+B2[s0+0];
        float gf=G[(s0+1)*132+b]+B2[s0+1];
        float gg=G[(s0+2)*132+b]+B2[s0+2];
        float go=G[(s0+3)*132+b]+B2[s0+3];
        float cn=sigf(gf)*c2s[cl]+sigf(gi)*tanhf(gg); c2s[cl]=cn;
        float h=sigf(go)*tanhf(cn);
        hh[cl]=tob(h); hl[cl]=tob(h-bfv(hh[cl])); }
      *(ushort4*)&g_h2h[b*HH+blk*4]=make_ushort4(hh[0],hh[1],hh[2],hh[3]);
      *(ushort4*)&g_h2l[b*HH+blk*4]=make_ushort4(hl[0],hl[1],hl[2],hl[3]);
    }
    gridbar();   // h2[t] visible everywhere
  }

  // final out column
  { u32 ph=ldcg32((const char*)g_h2h + blk*1024 + tid*4);
    u32 pl=ldcg32((const char*)g_h2l + blk*1024 + tid*4);
    ((float*)(sm+O_RED))[tid]=(bfv(ph)+bfv(pl))*wl0+(bfv(ph>>16)+bfv(pl>>16))*wl1;
    __syncthreads();
    if(warp==0){ float* R=(float*)(sm+O_RED); float sv=0.f;
#pragma unroll
      for(int j=0;j<8;j++) sv+=R[lane+j*32];
      for(int o=16;o;o>>=1) sv+=__shfl_down_sync(~0u,sv,o);
      if(lane==0) out[blk*TT+TT-1]=sv+blinv; } }
}

extern "C" void kernel_launch(void* const* d_in, const int* in_sizes, int n_in,
                              void* d_out, int out_size){
  const float* x   =(const float*)d_in[0];
  const float* Wih1=(const float*)d_in[1];
  const float* Whh1=(const float*)d_in[2];
  const float* bih1=(const float*)d_in[3];
  const float* bhh1=(const float*)d_in[4];
  const float* Wih2=(const float*)d_in[5];
  const float* Whh2=(const float*)d_in[6];
  const float* bih2=(const float*)d_in[7];
  const float* bhh2=(const float*)d_in[8];
  const float* Wlin=(const float*)d_in[9];
  const float* blin=(const float*)d_in[10];
  float* out=(float*)d_out;
  cudaFuncSetAttribute(lstm_mma, cudaFuncAttributeMaxDynamicSharedMemorySize, SMEMSZ);
  lstm_mma<<<NBLK,NTHR,SMEMSZ>>>(x,Wih1,Whh1,bih1,bhh1,Wih2,Whh2,bih2,bhh2,Wlin,blin,out);
}

// round 17
// speedup vs baseline: 1.2173x; 1.2173x over previous
#include <cuda_runtime.h>
#include <cuda_bf16.h>
typedef unsigned u32; typedef unsigned long long u64; typedef unsigned short u16;
#define NBLK 128
#define NTHR 256
#define TT 1024
#define HH 512

// h stored pre-split: separate bf16 hi and lo planes, [batch][k]
__device__ __align__(16) u16 g_h1h[2][128 * HH], g_h1l[2][128 * HH];
__device__ __align__(16) u16 g_h2h[128 * HH],    g_h2l[128 * HH];
__device__ float g_xt[TT * 128];
__device__ u32 g_cnt, g_epoch, g_dead;

// smem layout (bytes) — R14 footprint (3 stage slots), R13 semantics
#define O_W1  0          // weight tile: hi 16x1024B, lo at +16384 (32KB per matrix)
#define O_H2  32768
#define O_I2  65536
#define O_STG 98304      // 3 slots x 32768 (hi 16KB + lo 16KB), rows 128B swizzled
#define O_G   196608     // gates exchange: 16 x 132 f32 = 8448
#define O_WX  205056
#define O_BB1 205120
#define O_BB2 205184
#define O_RED 205248     // 256 f32
#define SMEMSZ 206336

__device__ __forceinline__ float sigf(float v){ return __fdividef(1.f, 1.f + __expf(-v)); }
__device__ __forceinline__ u32 s2u(const void* p){ u32 a; asm("{.reg .u64 t;cvta.to.shared.u64 t,%1;cvt.u32.u64 %0,t;}":"=r"(a):"l"(p)); return a; }
__device__ __forceinline__ u32 ldcg32(const void* p){ u32 v; asm volatile("ld.global.cg.u32 %0,[%1];":"=r"(v):"l"(p)); return v; }
__device__ __forceinline__ float bfv(u32 b){ u16 s=(u16)b; __nv_bfloat16 h=*(__nv_bfloat16*)&s; return __bfloat162float(h); }
__device__ __forceinline__ u16 tob(float f){ __nv_bfloat16 h=__float2bfloat16(f); return *(u16*)&h; }
__device__ __forceinline__ void ldm4(u32* r, u32 a){
  asm volatile("ldmatrix.sync.aligned.m8n8.x4.shared.b16 {%0,%1,%2,%3},[%4];"
    :"=r"(r[0]),"=r"(r[1]),"=r"(r[2]),"=r"(r[3]):"r"(a)); }
__device__ __forceinline__ void mma16816(float* c, const u32* a, const u32* b){
  asm volatile("mma.sync.aligned.m16n8k16.row.col.f32.bf16.bf16.f32 "
    "{%0,%1,%2,%3},{%4,%5,%6,%7},{%8,%9},{%0,%1,%2,%3};"
    :"+f"(c[0]),"+f"(c[1]),"+f"(c[2]),"+f"(c[3])
    :"r"(a[0]),"r"(a[1]),"r"(a[2]),"r"(a[3]),"r"(b[0]),"r"(b[1])); }
__device__ __forceinline__ void cpa16(u32 dst, const void* src){
  asm volatile("cp.async.cg.shared.global [%0],[%1],16;"::"r"(dst),"l"(src)); }
#define CPA_COMMIT() asm volatile("cp.async.commit_group;":::"memory")
#define CPA_WAIT0()  asm volatile("cp.async.wait_group 0;":::"memory")
#define CPA_WAIT1()  asm volatile("cp.async.wait_group 1;":::"memory")

// grid barrier with deadlock poison (proven R11-R14)
__device__ __forceinline__ void gridbar(){
  __syncthreads();
  if(threadIdx.x==0){
    u32 dead; asm volatile("ld.relaxed.gpu.u32 %0,[%1];":"=r"(dead):"l"(&g_dead));
    if(!dead){
      u32 e; asm volatile("ld.acquire.gpu.u32 %0,[%1];":"=r"(e):"l"(&g_epoch));
      u32 r; asm volatile("atom.add.release.gpu.u32 %0,[%1],%2;":"=r"(r):"l"(&g_cnt),"r"(1u));
      if(r==NBLK-1){
        asm volatile("st.relaxed.gpu.u32 [%0],%1;"::"l"(&g_cnt),"r"(0u));
        asm volatile("red.release.gpu.add.u32 [%0],%1;"::"l"(&g_epoch),"r"(1u));
      } else {
        u32 c, it=0;
        do{
          asm volatile("ld.acquire.gpu.u32 %0,[%1];":"=r"(c):"l"(&g_epoch));
          if(c!=e) break;
          asm volatile("ld.relaxed.gpu.u32 %0,[%1];":"=r"(dead):"l"(&g_dead));
          if(dead) break;
          if(++it > 20000000u){ atomicExch(&g_dead,1u); break; }
        } while(1);
      }
    }
  }
  __syncthreads();
}

// warp-private staging: warp w stages its own 16 rows (hi+lo) of chunk c; 8 cpa/lane
__device__ __forceinline__ void stage_warp(u32 stg, const u16* hiP, const u16* loP,
                                           int c, int warp, int lane){
#pragma unroll
  for(int i=0;i<8;i++){
    int u = lane + i*32;          // 0..255 = 2 planes x 16 rows x 8 atoms
    int p = u>>7;
    int rem = u&127;
    int r16 = rem>>3, atom = rem&7;
    int row = warp*16 + r16;
    const u16* src = (p ? loP : hiP) + row*HH + c*64 + atom*8;
    u32 dst = stg + (u32)(p*16384 + row*128 + (((atom ^ (row&7)))<<4));
    cpa16(dst, src);
  }
  CPA_COMMIT();
}

// one 64-k chunk (byte-identical to R13): 4 kt x (A hi/lo ldm4 + B hi/lo ldm4 + 6 mma)
__device__ __forceinline__ void gemm_chunk(u32 smb, int wbase, u32 stg, int c,
                                           int lane, int warp, float C[2][4]){
  const int krow = lane&15, khalf = lane>>4;
  const int brow = warp*16 + ((lane>>4)<<3) + (lane&7);
  const int bk   = (lane>>3)&1;
#pragma unroll
  for(int kt=0;kt<4;kt++){
    int aatom = c*8 + kt*2 + khalf;
    u32 aa = smb + (u32)wbase + (u32)(krow*1024) + (u32)(((aatom^(krow&7)))<<4);
    u32 ah[4], al[4]; ldm4(ah,aa); ldm4(al,aa+16384);
    int batom = kt*2 + bk;
    u32 ba = stg + (u32)(brow*128) + (u32)(((batom^(brow&7)))<<4);
    u32 bh[4], bl[4]; ldm4(bh,ba); ldm4(bl,ba+16384);
    mma16816(C[0],ah,bh);   mma16816(C[0],ah,bl);   mma16816(C[0],al,bh);
    mma16816(C[1],ah,bh+2); mma16816(C[1],ah,bl+2); mma16816(C[1],al,bh+2);
  }
}
// full 512-k GEMM: per-warp depth-2 pipeline, 3 slots, ZERO block syncs
__device__ __forceinline__ void gemm_full(u32 smb, const u16* hiP, const u16* loP, int wbase,
                                          float C[2][4], int lane, int warp){
  stage_warp(smb+O_STG,          hiP, loP, 0, warp, lane);
  stage_warp(smb+O_STG+32768u,   hiP, loP, 1, warp, lane);
#pragma unroll 1
  for(int c=0;c<8;c++){
    if(c<7){ CPA_WAIT1(); } else { CPA_WAIT0(); }
    __syncwarp();   // all lanes' copies for chunk c complete
    if(c<6) stage_warp(smb+O_STG+(u32)(((c+2)%3)*32768), hiP, loP, c+2, warp, lane);
    gemm_chunk(smb, wbase, smb+O_STG+(u32)((c%3)*32768), c, lane, warp, C);
  }
}

__global__ void __launch_bounds__(NTHR,1)
lstm_mma(const float* __restrict__ x, const float* __restrict__ Wih1, const float* __restrict__ Whh1,
         const float* __restrict__ bih1, const float* __restrict__ bhh1,
         const float* __restrict__ Wih2, const float* __restrict__ Whh2,
         const float* __restrict__ bih2, const float* __restrict__ bhh2,
         const float* __restrict__ Wlin, const float* __restrict__ blin, float* __restrict__ out){
  extern __shared__ __align__(128) char sm[];
  const int tid=threadIdx.x, blk=blockIdx.x, warp=tid>>5, lane=tid&31;
  const u32 smb = s2u(sm);

  // x transpose (each block its 8 t-columns)
  for(int i=tid;i<1024;i+=NTHR){ int t=blk*8+(i>>7), b=i&127; g_xt[t*128+b]=x[b*TT+t]; }
  // weights -> smem bf16 hi/lo, 1024B rows, swizzled atoms
  { const float* WS[3]={Whh1,Whh2,Wih2}; const int WO[3]={O_W1,O_H2,O_I2};
    for(int m=0;m<3;m++) for(int idx=tid; idx<16*HH; idx+=NTHR){
      int s=idx&15, k=idx>>4; int r=(s&3)*HH + blk*4 + (s>>2);
      float w=WS[m][r*HH+k]; u16 hb=tob(w); u16 lb=tob(w-bfv(hb));
      u32 off=(u32)(s*1024) + (u32)((((k>>3)^(s&7))<<4)) + (u32)((k&7)*2);
      *(u16*)(sm+WO[m]+off)=hb; *(u16*)(sm+WO[m]+16384+off)=lb; } }
  if(tid<16){ int s=tid, r=(s&3)*HH + blk*4 + (s>>2);
    ((float*)(sm+O_WX))[s]=Wih1[r];
    ((float*)(sm+O_BB1))[s]=bih1[r]+bhh1[r];
    ((float*)(sm+O_BB2))[s]=bih2[r]+bhh2[r]; }
  const float wl0=Wlin[tid*2], wl1=Wlin[tid*2+1], blinv=blin[0];
  for(int i=tid;i<512;i+=NTHR){ int b=i>>2, c=i&3; int o=b*HH+blk*4+c;
    g_h1h[0][o]=0; g_h1l[0][o]=0; g_h2h[o]=0; g_h2l[o]=0; }
  __syncthreads();
  gridbar();

  float c1s[4]={0,0,0,0}, c2s[4]={0,0,0,0};   // cells: threads 0-127, batch=tid, 4 cols

  for(int t=0;t<TT;t++){
    const u16* h1rh = g_h1h[t&1];      const u16* h1rl = g_h1l[t&1];
    u16* h1wh = g_h1h[(t&1)^1];        u16* h1wl = g_h1l[(t&1)^1];

    // out[t-1] partials (h2 stable since last gridbar)
    if(t>0){
      u32 ph=ldcg32((const char*)g_h2h + blk*1024 + tid*4);
      u32 pl=ldcg32((const char*)g_h2l + blk*1024 + tid*4);
      ((float*)(sm+O_RED))[tid]=(bfv(ph)+bfv(pl))*wl0+(bfv(ph>>16)+bfv(pl>>16))*wl1;
    }

    float C1[2][4]={{0,0,0,0},{0,0,0,0}}, C2[2][4]={{0,0,0,0},{0,0,0,0}};
    gemm_full(smb, h1rh, h1rl, O_W1, C1, lane, warp);   // gates1 = Whh1*h1
    gemm_full(smb, g_h2h, g_h2l, O_H2, C2, lane, warp); // gates2  = Whh2*h2

    // epilogue A: exchange C1 -> G
    { float* G=(float*)(sm+O_G);
#pragma unroll
      for(int nt=0;nt<2;nt++){ int n0=warp*16+nt*8+(lane&3)*2; int rr=lane>>2;
        *(float2*)&G[rr*132+n0]     = make_float2(C1[nt][0],C1[nt][1]);
        *(float2*)&G[(rr+8)*132+n0] = make_float2(C1[nt][2],C1[nt][3]); } }
    __syncthreads();
    if(t>0 && warp==7){ float* R=(float*)(sm+O_RED); float sv=0.f;
#pragma unroll
      for(int j=0;j<8;j++) sv+=R[lane+j*32];
      for(int o=16;o;o>>=1) sv+=__shfl_down_sync(~0u,sv,o);
      if(lane==0) out[blk*TT+t-1]=sv+blinv; }
    if(tid<128){
      float* G=(float*)(sm+O_G); float* WX=(float*)(sm+O_WX); float* B1=(float*)(sm+O_BB1);
      int b=tid; float xv=g_xt[t*128+b];
      u16 hh[4], hl[4];
#pragma unroll
      for(int cl=0;cl<4;cl++){ int s0=cl*4;
        float gi=G[(s0+0)*132+b]+B1[s0+0]+xv*WX[s0+0];
        float gf=G[(s0+1)*132+b]+B1[s0+1]+xv*WX[s0+1];
        float gg=G[(s0+2)*132+b]+B1[s0+2]+xv*WX[s0+2];
        float go=G[(s0+3)*132+b]+B1[s0+3]+xv*WX[s0+3];
        float cn=sigf(gf)*c1s[cl]+sigf(gi)*tanhf(gg); c1s[cl]=cn;
        float h=sigf(go)*tanhf(cn);
        hh[cl]=tob(h); hl[cl]=tob(h-bfv(hh[cl])); }
      *(ushort4*)&h1wh[b*HH+blk*4]=make_ushort4(hh[0],hh[1],hh[2],hh[3]);
      *(ushort4*)&h1wl[b*HH+blk*4]=make_ushort4(hl[0],hl[1],hl[2],hl[3]);
    }
    gridbar();   // h1[t] visible everywhere

    // phase B: gates2 += Wih2 * h1_new
    gemm_full(smb, h1wh, h1wl, O_I2, C2, lane, warp);

    { float* G=(float*)(sm+O_G);
#pragma unroll
      for(int nt=0;nt<2;nt++){ int n0=warp*16+nt*8+(lane&3)*2; int rr=lane>>2;
        *(float2*)&G[rr*132+n0]     = make_float2(C2[nt][0],C2[nt][1]);
        *(float2*)&G[(rr+8)*132+n0] = make_float2(C2[nt][2],C2[nt][3]); } }
    __syncthreads();
    if(tid<128){
      float* G=(float*)(sm+O_G); float* B2=(float*)(sm+O_BB2);
      int b=tid;
      u16 hh[4], hl[4];
#pragma unroll
      for(int cl=0;cl<4;cl++){ int s0=cl*4;
        float gi=G[(s0+0)*132+b]+B2[s0+0];
        float gf=G[(s0+1)*132+b]+B2[s0+1];
        float gg=G[(s0+2)*132+b]+B2[s0+2];
        float go=G[(s0+3)*132+b]+B2[s0+3];
        float cn=sigf(gf)*c2s[cl]+sigf(gi)*tanhf(gg); c2s[cl]=cn;
        float h=sigf(go)*tanhf(cn);
        hh[cl]=tob(h); hl[cl]=tob(h-bfv(hh[cl])); }
      *(ushort4*)&g_h2h[b*HH+blk*4]=make_ushort4(hh[0],hh[1],hh[2],hh[3]);
      *(ushort4*)&g_h2l[b*HH+blk*4]=make_ushort4(hl[0],hl[1],hl[2],hl[3]);
    }
    gridbar();   // h2[t] visible everywhere
  }

  // final out column
  { u32 ph=ldcg32((const char*)g_h2h + blk*1024 + tid*4);
    u32 pl=ldcg32((const char*)g_h2l + blk*1024 + tid*4);
    ((float*)(sm+O_RED))[tid]=(bfv(ph)+bfv(pl))*wl0+(bfv(ph>>16)+bfv(pl>>16))*wl1;
    __syncthreads();
    if(warp==0){ float* R=(float*)(sm+O_RED); float sv=0.f;
#pragma unroll
      for(int j=0;j<8;j++) sv+=R[lane+j*32];
      for(int o=16;o;o>>=1) sv+=__shfl_down_sync(~0u,sv,o);
      if(lane==0) out[blk*TT+TT-1]=sv+blinv; } }
}

extern "C" void kernel_launch(void* const* d_in, const int* in_sizes, int n_in,
                              void* d_out, int out_size){
  const float* x   =(const float*)d_in[0];
  const float* Wih1=(const float*)d_in[1];
  const float* Whh1=(const float*)d_in[2];
  const float* bih1=(const float*)d_in[3];
  const float* bhh1=(const float*)d_in[4];
  const float* Wih2=(const float*)d_in[5];
  const float* Whh2=(const float*)d_in[6];
  const float* bih2=(const float*)d_in[7];
  const float* bhh2=(const float*)d_in[8];
  const float* Wlin=(const float*)d_in[9];
  const float* blin=(const float*)d_in[10];
  float* out=(float*)d_out;
  cudaFuncSetAttribute(lstm_mma, cudaFuncAttributeMaxDynamicSharedMemorySize, SMEMSZ);
  lstm_mma<<<NBLK,NTHR,SMEMSZ>>>(x,Wih1,Whh1,bih1,bhh1,Wih2,Whh2,bih2,bhh2,Wlin,blin,out);
}